// round 11
// baseline (speedup 1.0000x reference)
#include <cuda_runtime.h>
#include <cuda_bf16.h>
#include <cstdint>
#include <cstring>

#define H_    56
#define W_    56
#define NH_   12
#define HD    64
#define NTOK  3137          // 56*56 + 1
#define C_    768
#define C3    2304
#define B_    8
#define MTOT  (B_ * NTOK)   // 25096
#define KDIM  768
#define BK    32
#define NSTG  (KDIM / BK)   // 24

// ---------------- scratch (__device__ globals; no cudaMalloc allowed) -------
__device__ __nv_bfloat16 g_qh [(size_t)MTOT * C3];   // QKV hi/lo (bf16 split)
__device__ __nv_bfloat16 g_ql [(size_t)MTOT * C3];
__device__ float         g_att[(size_t)MTOT * C_];   // fp32 row-partial
__device__ float         g_sc [(size_t)B_ * NH_ * H_ * W_ * 64]; // col scores/probs
__device__ __nv_bfloat16 g_xh [(size_t)MTOT * C_];   // x split hi/lo
__device__ __nv_bfloat16 g_xl [(size_t)MTOT * C_];
__device__ __nv_bfloat16 g_ath[(size_t)MTOT * C_];   // attention out hi/lo
__device__ __nv_bfloat16 g_atl[(size_t)MTOT * C_];
__device__ __nv_bfloat16 g_wqh[(size_t)C3 * C_];     // W_qkv^T split  [N,K]
__device__ __nv_bfloat16 g_wql[(size_t)C3 * C_];
__device__ __nv_bfloat16 g_wph[(size_t)C_ * C_];     // W_proj^T split [N,K]
__device__ __nv_bfloat16 g_wpl[(size_t)C_ * C_];

__device__ __forceinline__ void split2(float v, __nv_bfloat16& h, __nv_bfloat16& l) {
    h = __float2bfloat16(v);
    l = __float2bfloat16(v - __bfloat162float(h));
}
__device__ __forceinline__ uint32_t pack2(__nv_bfloat16 a, __nv_bfloat16 b) {
    return (uint32_t)__bfloat16_as_ushort(a) |
           ((uint32_t)__bfloat16_as_ushort(b) << 16);
}
__device__ __forceinline__ uint32_t su32(const void* p) {
    uint32_t a;
    asm("{ .reg .u64 t; cvta.to.shared.u64 t, %1; cvt.u32.u64 %0, t; }"
        : "=r"(a) : "l"(p));
    return a;
}
__device__ __forceinline__ void cp16(uint32_t dst, const void* src, bool ok) {
    int sz = ok ? 16 : 0;
    asm volatile("cp.async.cg.shared.global [%0], [%1], 16, %2;"
                 :: "r"(dst), "l"(src), "r"(sz) : "memory");
}
__device__ __forceinline__ void mma16816(float* c, const uint32_t* a, const uint32_t* b) {
    asm volatile(
        "mma.sync.aligned.m16n8k16.row.col.f32.bf16.bf16.f32 "
        "{%0,%1,%2,%3}, {%4,%5,%6,%7}, {%8,%9}, {%0,%1,%2,%3};"
        : "+f"(c[0]), "+f"(c[1]), "+f"(c[2]), "+f"(c[3])
        : "r"(a[0]), "r"(a[1]), "r"(a[2]), "r"(a[3]), "r"(b[0]), "r"(b[1]));
}
__device__ __forceinline__ void ldsm4(uint32_t& r0, uint32_t& r1, uint32_t& r2,
                                      uint32_t& r3, uint32_t addr) {
    asm volatile("ldmatrix.sync.aligned.m8n8.x4.shared.b16 {%0,%1,%2,%3}, [%4];"
                 : "=r"(r0), "=r"(r1), "=r"(r2), "=r"(r3) : "r"(addr));
}
__device__ __forceinline__ void ldsm4t(uint32_t& r0, uint32_t& r1, uint32_t& r2,
                                       uint32_t& r3, uint32_t addr) {
    asm volatile("ldmatrix.sync.aligned.m8n8.x4.trans.shared.b16 {%0,%1,%2,%3}, [%4];"
                 : "=r"(r0), "=r"(r1), "=r"(r2), "=r"(r3) : "r"(addr));
}

// ---------------- pre-pass: fp32 -> bf16 hi/lo ------------------------------
__global__ __launch_bounds__(256) void k_split(
    const float* __restrict__ in, __nv_bfloat16* __restrict__ hi,
    __nv_bfloat16* __restrict__ lo, int n4)
{
    int i = blockIdx.x * 256 + threadIdx.x;
    if (i >= n4) return;
    float4 v = ((const float4*)in)[i];
    __nv_bfloat16 hv[4], lv[4];
    split2(v.x, hv[0], lv[0]);
    split2(v.y, hv[1], lv[1]);
    split2(v.z, hv[2], lv[2]);
    split2(v.w, hv[3], lv[3]);
    ((uint2*)hi)[i] = *(uint2*)hv;
    ((uint2*)lo)[i] = *(uint2*)lv;
}

// ---------------- pre-pass: transpose + split weights [R,Cn] -> [Cn,R] ------
__global__ __launch_bounds__(256) void k_tsplit(
    const float* __restrict__ W, __nv_bfloat16* __restrict__ th,
    __nv_bfloat16* __restrict__ tl, int R, int Cn)
{
    __shared__ float t[32][33];
    int x = blockIdx.x * 32 + threadIdx.x;
    int y = blockIdx.y * 32 + threadIdx.y;
#pragma unroll
    for (int j = 0; j < 32; j += 8)
        t[threadIdx.y + j][threadIdx.x] = W[(size_t)(y + j) * Cn + x];
    __syncthreads();
    int ox = blockIdx.y * 32 + threadIdx.x;
    int oy = blockIdx.x * 32 + threadIdx.y;
#pragma unroll
    for (int j = 0; j < 32; j += 8) {
        float v = t[threadIdx.x][threadIdx.y + j];
        __nv_bfloat16 h, l;
        split2(v, h, l);
        th[(size_t)(oy + j) * R + ox] = h;
        tl[(size_t)(oy + j) * R + ox] = l;
    }
}

// ---------------- bf16x3 GEMM: mma.sync + ldmatrix, 3-stage swizzled --------
#define TS2     8192                 // one tensor tile per stage
#define STG2    (4 * TS2)            // 32 KB per stage
#define GEMM_SMEM (3 * STG2)         // 96 KB

__global__ __launch_bounds__(256) void gemm_mma(
    const __nv_bfloat16* __restrict__ Ah, const __nv_bfloat16* __restrict__ Al,
    const __nv_bfloat16* __restrict__ Bh, const __nv_bfloat16* __restrict__ Bl,
    float* __restrict__ Cc, const float* __restrict__ bias,
    __nv_bfloat16* __restrict__ Oh, __nv_bfloat16* __restrict__ Ol,
    int M, int N)
{
    extern __shared__ __align__(128) char smem[];
    const uint32_t sb = su32(smem);
    const int tid  = threadIdx.x;
    const int wid  = tid >> 5, lane = tid & 31;
    const int gid  = lane >> 2, tig = lane & 3;
    const int wm   = wid & 1, wn = wid >> 1;          // 2 x 4 warp grid
    const int row0 = blockIdx.y * 128, col0 = blockIdx.x * 128;

    float acc[4][4][4];
#pragma unroll
    for (int i = 0; i < 4; ++i)
#pragma unroll
        for (int j = 0; j < 4; ++j)
#pragma unroll
            for (int k = 0; k < 4; ++k) acc[i][j][k] = 0.f;

    const int rlA = (lane & 7) + ((lane >> 3) & 1) * 8;
    const int kcA = (lane >> 4) & 1;
    const int swA = (rlA >> 1) & 3;
    const int rlB = (lane & 7) + ((lane >> 4) & 1) * 8;
    const int kcB = (lane >> 3) & 1;
    const int swB = (rlB >> 1) & 3;
    const uint32_t aRow = (uint32_t)(wm * 64 + rlA) * 64u;
    const uint32_t bRow = (uint32_t)(wn * 32 + rlB) * 64u;

    const int r0c = tid >> 2, j0c = tid & 3;
    const int r1c = (tid + 256) >> 2, j1c = tid & 3;

    auto issue = [&](int c) {
        const int k0 = c * BK;
        const uint32_t stg = sb + (uint32_t)(c % 3) * STG2;
#pragma unroll
        for (int rep = 0; rep < 2; ++rep) {
            const int row = rep ? r1c : r0c;
            const int j   = rep ? j1c : j0c;
            const uint32_t d = stg + (uint32_t)row * 64u
                             + (uint32_t)((j ^ ((row >> 1) & 3)) * 16);
            const int grA = row0 + row;
            const bool okA = grA < M;
            const size_t aoff = (size_t)(okA ? grA : 0) * KDIM + k0 + j * 8;
            cp16(d,           Ah + aoff, okA);
            cp16(d + TS2,     Al + aoff, okA);
            const size_t boff = (size_t)(col0 + row) * KDIM + k0 + j * 8;
            cp16(d + 2 * TS2, Bh + boff, true);
            cp16(d + 3 * TS2, Bl + boff, true);
        }
        asm volatile("cp.async.commit_group;" ::: "memory");
    };

    issue(0);
    issue(1);

    for (int c = 0; c < NSTG; ++c) {
        asm volatile("cp.async.wait_group 1;" ::: "memory");
        __syncthreads();
        if (c + 2 < NSTG) issue(c + 2);

        const uint32_t stg = sb + (uint32_t)(c % 3) * STG2;

#pragma unroll
        for (int kk = 0; kk < 2; ++kk) {
            const uint32_t aCh = (uint32_t)(((kcA + 2 * kk) ^ swA) * 16);
            const uint32_t bCh = (uint32_t)(((kcB + 2 * kk) ^ swB) * 16);
            uint32_t ah[4][4], al[4][4], bh[4][2], bl[4][2];
#pragma unroll
            for (int mt = 0; mt < 4; ++mt) {
                const uint32_t aAd = stg + aRow + mt * (16 * 64) + aCh;
                ldsm4(ah[mt][0], ah[mt][1], ah[mt][2], ah[mt][3], aAd);
                ldsm4(al[mt][0], al[mt][1], al[mt][2], al[mt][3], aAd + TS2);
            }
#pragma unroll
            for (int pr = 0; pr < 2; ++pr) {
                const uint32_t bAd = stg + bRow + pr * (16 * 64) + bCh;
                ldsm4(bh[2 * pr][0], bh[2 * pr][1], bh[2 * pr + 1][0], bh[2 * pr + 1][1],
                      bAd + 2 * TS2);
                ldsm4(bl[2 * pr][0], bl[2 * pr][1], bl[2 * pr + 1][0], bl[2 * pr + 1][1],
                      bAd + 3 * TS2);
            }
#pragma unroll
            for (int mt = 0; mt < 4; ++mt)
#pragma unroll
                for (int nt = 0; nt < 4; ++nt) mma16816(acc[mt][nt], ah[mt], bh[nt]);
#pragma unroll
            for (int mt = 0; mt < 4; ++mt)
#pragma unroll
                for (int nt = 0; nt < 4; ++nt) mma16816(acc[mt][nt], ah[mt], bl[nt]);
#pragma unroll
            for (int mt = 0; mt < 4; ++mt)
#pragma unroll
                for (int nt = 0; nt < 4; ++nt) mma16816(acc[mt][nt], al[mt], bh[nt]);
        }
    }

    // epilogue
#pragma unroll
    for (int mt = 0; mt < 4; ++mt) {
        const int gr = row0 + wm * 64 + mt * 16 + gid;
#pragma unroll
        for (int nt = 0; nt < 4; ++nt) {
            const int gc = col0 + wn * 32 + nt * 8 + tig * 2;
            if (Oh != nullptr) {
                if (gr < M) {
                    __nv_bfloat16 h0, l0, h1, l1;
                    split2(acc[mt][nt][0], h0, l0);
                    split2(acc[mt][nt][1], h1, l1);
                    *(uint32_t*)(Oh + (size_t)gr * N + gc) = pack2(h0, h1);
                    *(uint32_t*)(Ol + (size_t)gr * N + gc) = pack2(l0, l1);
                }
                if (gr + 8 < M) {
                    __nv_bfloat16 h0, l0, h1, l1;
                    split2(acc[mt][nt][2], h0, l0);
                    split2(acc[mt][nt][3], h1, l1);
                    *(uint32_t*)(Oh + (size_t)(gr + 8) * N + gc) = pack2(h0, h1);
                    *(uint32_t*)(Ol + (size_t)(gr + 8) * N + gc) = pack2(l0, l1);
                }
            } else {
                float b0 = 0.f, b1 = 0.f;
                if (bias) { b0 = __ldg(bias + gc); b1 = __ldg(bias + gc + 1); }
                if (gr < M) {
                    float2 v0 = make_float2(acc[mt][nt][0] + b0, acc[mt][nt][1] + b1);
                    *(float2*)(Cc + (size_t)gr * N + gc) = v0;
                }
                if (gr + 8 < M) {
                    float2 v1 = make_float2(acc[mt][nt][2] + b0, acc[mt][nt][3] + b1);
                    *(float2*)(Cc + (size_t)(gr + 8) * N + gc) = v1;
                }
            }
        }
    }
}

// ============================================================================
// Attention MMA helpers: 64x64 bf16 tiles, 128B rows, chunk swizzle c^(row&7)
// ============================================================================
#define ATS 8192   // one 64x64 bf16 tile

// per-warp score/agg MMA over a 64x64x64 tile set (3-pass bf16x3)
// A tiles at sA(h)/sA+ATS(l); B tiles at sB(h)/sB+ATS(l). acc[8][4].
// trans=false: B rows = n (keys), k along row.  trans=true: B rows = k, n along row.
template <bool TRANS>
__device__ __forceinline__ void att_mma64(
    float (&acc)[8][4], uint32_t sA, uint32_t sB, int m0, int lane)
{
    const int rA = (lane & 7) + ((lane >> 3) & 1) * 8;  // A row within m16
    const int cA = (lane >> 4) & 1;                      // A k-chunk bit
#pragma unroll
    for (int s = 0; s < 4; ++s) {
        uint32_t ah[4], al[4];
        {
            const int row = m0 + rA;
            const uint32_t ad = sA + (uint32_t)row * 128u
                              + (uint32_t)(((2 * s + cA) ^ (row & 7)) * 16);
            ldsm4(ah[0], ah[1], ah[2], ah[3], ad);
            ldsm4(al[0], al[1], al[2], al[3], ad + ATS);
        }
        uint32_t bh[8][2], bl[8][2];
#pragma unroll
        for (int p = 0; p < 4; ++p) {
            uint32_t ad;
            if (TRANS) {
                const int row = s * 16 + (lane & 7) + ((lane >> 3) & 1) * 8;
                const int ch  = 2 * p + ((lane >> 4) & 1);
                ad = sB + (uint32_t)row * 128u + (uint32_t)((ch ^ (row & 7)) * 16);
            } else {
                const int row = p * 16 + (lane & 7) + ((lane >> 4) & 1) * 8;
                const int ch  = 2 * s + ((lane >> 3) & 1);
                ad = sB + (uint32_t)row * 128u + (uint32_t)((ch ^ (row & 7)) * 16);
            }
            if (TRANS) {
                ldsm4t(bh[2 * p][0], bh[2 * p][1], bh[2 * p + 1][0], bh[2 * p + 1][1], ad);
                ldsm4t(bl[2 * p][0], bl[2 * p][1], bl[2 * p + 1][0], bl[2 * p + 1][1], ad + ATS);
            } else {
                ldsm4(bh[2 * p][0], bh[2 * p][1], bh[2 * p + 1][0], bh[2 * p + 1][1], ad);
                ldsm4(bl[2 * p][0], bl[2 * p][1], bl[2 * p + 1][0], bl[2 * p + 1][1], ad + ATS);
            }
        }
#pragma unroll
        for (int nt = 0; nt < 8; ++nt) mma16816(acc[nt], ah, bh[nt]);
#pragma unroll
        for (int nt = 0; nt < 8; ++nt) mma16816(acc[nt], ah, bl[nt]);
#pragma unroll
        for (int nt = 0; nt < 8; ++nt) mma16816(acc[nt], al, bh[nt]);
    }
}

// load one 64-row bf16 tile pair (hi/lo) from qkv, rows mapped by functor
#define TILE_LOAD(Th, Tl, NMAP, RMAX, GOFF)                                    \
    for (int idx = tid; idx < 512; idx += 128) {                               \
        const int r = idx >> 3, cc = idx & 7;                                  \
        const uint32_t d = (uint32_t)r * 128u + (uint32_t)((cc ^ (r & 7)) * 16); \
        uint4 vh = make_uint4(0, 0, 0, 0), vl = vh;                            \
        if (r < (RMAX)) {                                                      \
            const int n = (NMAP);                                              \
            const size_t off = (size_t)n * C3 + (GOFF) + cc * 8;               \
            vh = *(const uint4*)(qh + off);                                    \
            vl = *(const uint4*)(ql + off);                                    \
        }                                                                      \
        *(uint4*)((Th) + d) = vh;                                              \
        *(uint4*)((Tl) + d) = vl;                                              \
    }

// ============================================================================
// Phase 1: column scores via MMA. Block=(w, head, b), 128 threads.
// ============================================================================
__global__ __launch_bounds__(128) void k_colscore(
    const __nv_bfloat16* __restrict__ qhg, const __nv_bfloat16* __restrict__ qlg,
    float* __restrict__ sc)
{
    __shared__ __align__(16) char sm[4 * ATS];
    const int w = blockIdx.x, head = blockIdx.y, b = blockIdx.z;
    const int tid = threadIdx.x, wid = tid >> 5, lane = tid & 31;
    const __nv_bfloat16* qh = qhg + (size_t)b * NTOK * C3;
    const __nv_bfloat16* ql = qlg + (size_t)b * NTOK * C3;
    const int qoff = head * HD;

    char* T0 = sm;              // Qh
    char* T1 = sm + ATS;        // Ql
    char* T2 = sm + 2 * ATS;    // Kh
    char* T3 = sm + 3 * ATS;    // Kl

    TILE_LOAD(T0, T1, 1 + r * W_ + w, 56, qoff)
    { const __nv_bfloat16* qh2 = qh; const __nv_bfloat16* ql2 = ql;
      (void)qh2; (void)ql2; }
    TILE_LOAD(T2, T3, (r == 0) ? 0 : (1 + (r - 1) * W_ + w), 57, C_ + qoff)
    __syncthreads();

    float acc[8][4];
#pragma unroll
    for (int i = 0; i < 8; ++i)
#pragma unroll
        for (int j = 0; j < 4; ++j) acc[i][j] = 0.f;

    const uint32_t sA = su32(T0), sB = su32(T2);
    att_mma64<false>(acc, sA, sB, wid * 16, lane);

    float* out = sc + ((((size_t)b * NH_ + head) * H_) * W_ + w) * 64;
    const int crow = wid * 16 + (lane >> 2);
    const int ccol = (lane & 3) * 2;
#pragma unroll
    for (int nt = 0; nt < 8; ++nt)
#pragma unroll
        for (int i = 0; i < 4; ++i) {
            const int row = crow + (i >> 1) * 8;
            const int col = nt * 8 + ccol + (i & 1);
            if (row < 56 && col < 57)
                out[(size_t)row * (W_ * 64) + col] = acc[nt][i] * 0.125f;
        }
}

// ============================================================================
// Phase 2: row scores (MMA) + full softmax + row P·V (MMA).
// Block=(h, head, b), 128 threads, dynamic smem.
// ============================================================================
#define PST 132
#define RF_SMEM (4 * ATS + 64 * PST * 4)   // 32768 + 33792 = 66560

__global__ __launch_bounds__(128) void k_rowfused(
    const __nv_bfloat16* __restrict__ qhg, const __nv_bfloat16* __restrict__ qlg,
    float* __restrict__ sc, float* __restrict__ attp)
{
    extern __shared__ __align__(16) char dsm[];
    char* T0 = dsm;              // Qh -> Pbh
    char* T1 = dsm + ATS;        // Ql -> Pbl
    char* T2 = dsm + 2 * ATS;    // Kh -> Vh
    char* T3 = dsm + 3 * ATS;    // Kl -> Vl
    float* P = (float*)(dsm + 4 * ATS);

    const int h = blockIdx.x, head = blockIdx.y, b = blockIdx.z;
    const int tid = threadIdx.x, wid = tid >> 5, lane = tid & 31;
    const __nv_bfloat16* qh = qhg + (size_t)b * NTOK * C3;
    const __nv_bfloat16* ql = qlg + (size_t)b * NTOK * C3;
    const int qoff = head * HD;
    const int nrow0 = 1 + h * W_;

    TILE_LOAD(T0, T1, nrow0 + r, 56, qoff)
    TILE_LOAD(T2, T3, nrow0 + r, 56, C_ + qoff)
    __syncthreads();

    // row scores
    {
        float acc[8][4];
#pragma unroll
        for (int i = 0; i < 8; ++i)
#pragma unroll
            for (int j = 0; j < 4; ++j) acc[i][j] = 0.f;
        att_mma64<false>(acc, su32(T0), su32(T2), wid * 16, lane);

        const int crow = wid * 16 + (lane >> 2);
        const int ccol = (lane & 3) * 2;
#pragma unroll
        for (int nt = 0; nt < 8; ++nt)
#pragma unroll
            for (int i = 0; i < 4; ++i) {
                const int row = crow + (i >> 1) * 8;
                const int col = nt * 8 + ccol + (i & 1);
                float v = acc[nt][i] * 0.125f;
                if (col == row || col >= 56) v = -1e30f;
                P[row * PST + 60 + col] = v;
            }
    }
    __syncthreads();

    // load col scores + V tiles (K space reuse)
    {
        const float* scb = sc + ((((size_t)b * NH_ + head) * H_ + h) * W_) * 64;
        for (int idx = tid; idx < 56 * 57; idx += 128) {
            const int q = idx / 57, j = idx % 57;
            P[q * PST + j] = scb[(size_t)q * 64 + j];
        }
    }
    TILE_LOAD(T2, T3, nrow0 + r, 56, 2 * C_ + qoff)
    __syncthreads();

    // softmax over 113 (cols 0..56 and 60..115)
    if (tid < 56) {
        float* row = P + tid * PST;
        float m = -1e30f;
#pragma unroll 4
        for (int j = 0; j < 57; ++j) m = fmaxf(m, row[j]);
#pragma unroll 4
        for (int j = 60; j < 116; ++j) m = fmaxf(m, row[j]);
        float s = 0.f;
#pragma unroll 4
        for (int j = 0; j < 57; ++j) { float e = __expf(row[j] - m); row[j] = e; s += e; }
#pragma unroll 4
        for (int j = 60; j < 116; ++j) { float e = __expf(row[j] - m); row[j] = e; s += e; }
        const float inv = 1.f / s;
#pragma unroll 4
        for (int j = 0; j < 57; ++j) row[j] *= inv;
#pragma unroll 4
        for (int j = 60; j < 116; ++j) row[j] *= inv;
    }
    __syncthreads();

    // write col probs back; convert row probs to bf16 hi/lo tiles (over Q space)
    {
        float* scb = sc + ((((size_t)b * NH_ + head) * H_ + h) * W_) * 64;
        for (int idx = tid; idx < 56 * 57; idx += 128) {
            const int q = idx / 57, j = idx % 57;
            scb[(size_t)q * 64 + j] = P[q * PST + j];
        }
        for (int idx = tid; idx < 4096; idx += 128) {
            const int q = idx >> 6, k = idx & 63;
            float v = (q < 56 && k < 56) ? P[q * PST + 60 + k] : 0.f;
            __nv_bfloat16 hh, ll;
            split2(v, hh, ll);
            const uint32_t d = (uint32_t)q * 128u
                             + (uint32_t)((((k >> 3) ^ (q & 7)) * 16) + (k & 7) * 2);
            *(__nv_bfloat16*)(T0 + d) = hh;
            *(__nv_bfloat16*)(T1 + d) = ll;
        }
    }
    __syncthreads();

    // row aggregation: P[64(q) x 64(k)] @ V[64(k) x 64(d)] (V trans-loaded)
    {
        float acc[8][4];
#pragma unroll
        for (int i = 0; i < 8; ++i)
#pragma unroll
            for (int j = 0; j < 4; ++j) acc[i][j] = 0.f;
        att_mma64<true>(acc, su32(T0), su32(T2), wid * 16, lane);

        const int crow = wid * 16 + (lane >> 2);
        const int ccol = (lane & 3) * 2;
#pragma unroll
        for (int nt = 0; nt < 8; ++nt) {
            const int col = nt * 8 + ccol;
            const int r0 = crow, r1 = crow + 8;
            if (r0 < 56)
                *(float2*)(attp + ((size_t)b * NTOK + nrow0 + r0) * C_ + qoff + col)
                    = make_float2(acc[nt][0], acc[nt][1]);
            if (r1 < 56)
                *(float2*)(attp + ((size_t)b * NTOK + nrow0 + r1) * C_ + qoff + col)
                    = make_float2(acc[nt][2], acc[nt][3]);
        }
    }
}

// ============================================================================
// Phase 3: column aggregation (MMA) + final hi/lo emit. Block=(w, head, b).
// ============================================================================
__global__ __launch_bounds__(128) void k_colagg(
    const __nv_bfloat16* __restrict__ qhg, const __nv_bfloat16* __restrict__ qlg,
    const float* __restrict__ sc, const float* __restrict__ attp,
    __nv_bfloat16* __restrict__ outh, __nv_bfloat16* __restrict__ outl)
{
    __shared__ __align__(16) char sm[4 * ATS];
    char* T0 = sm;              // Pch
    char* T1 = sm + ATS;        // Pcl
    char* T2 = sm + 2 * ATS;    // Vh
    char* T3 = sm + 3 * ATS;    // Vl
    const int w = blockIdx.x, head = blockIdx.y, b = blockIdx.z;
    const int tid = threadIdx.x, wid = tid >> 5, lane = tid & 31;
    const __nv_bfloat16* qh = qhg + (size_t)b * NTOK * C3;
    const __nv_bfloat16* ql = qlg + (size_t)b * NTOK * C3;
    const int qoff = head * HD;

    TILE_LOAD(T2, T3, (r == 0) ? 0 : (1 + (r - 1) * W_ + w), 57, 2 * C_ + qoff)
    {
        const float* scb = sc + (((size_t)b * NH_ + head) * H_) * (W_ * 64)
                         + (size_t)w * 64;
        for (int idx = tid; idx < 4096; idx += 128) {
            const int q = idx >> 6, k = idx & 63;
            float v = (q < 56 && k < 57) ? scb[(size_t)q * (W_ * 64) + k] : 0.f;
            __nv_bfloat16 hh, ll;
            split2(v, hh, ll);
            const uint32_t d = (uint32_t)q * 128u
                             + (uint32_t)((((k >> 3) ^ (q & 7)) * 16) + (k & 7) * 2);
            *(__nv_bfloat16*)(T0 + d) = hh;
            *(__nv_bfloat16*)(T1 + d) = ll;
        }
    }
    __syncthreads();

    float acc[8][4];
#pragma unroll
    for (int i = 0; i < 8; ++i)
#pragma unroll
        for (int j = 0; j < 4; ++j) acc[i][j] = 0.f;
    att_mma64<true>(acc, su32(T0), su32(T2), wid * 16, lane);

    const int crow = wid * 16 + (lane >> 2);
    const int ccol = (lane & 3) * 2;
#pragma unroll
    for (int nt = 0; nt < 8; ++nt) {
        const int col = nt * 8 + ccol;
#pragma unroll
        for (int half = 0; half < 2; ++half) {
            const int row = crow + half * 8;
            if (row >= 56) continue;
            const size_t off = ((size_t)b * NTOK + 1 + row * W_ + w) * C_ + qoff + col;
            const float2 rp = *(const float2*)(attp + off);
            __nv_bfloat16 h0, l0, h1, l1;
            split2(acc[nt][2 * half + 0] + rp.x, h0, l0);
            split2(acc[nt][2 * half + 1] + rp.y, h1, l1);
            *(uint32_t*)(outh + off) = pack2(h0, h1);
            *(uint32_t*)(outl + off) = pack2(l0, l1);
        }
    }
}

// ---------------- CLS-token attention (reads bf16 hi/lo) --------------------
__global__ __launch_bounds__(256) void attn_cls(
    const __nv_bfloat16* __restrict__ qhg, const __nv_bfloat16* __restrict__ qlg,
    __nv_bfloat16* __restrict__ outh, __nv_bfloat16* __restrict__ outl)
{
    const int b  = blockIdx.x / NH_;
    const int nh = blockIdx.x % NH_;
    const int tid = threadIdx.x;

    __shared__ float qs[HD];
    __shared__ float scs[NTOK];
    __shared__ float red[256];
    __shared__ float part[4][HD];

    const __nv_bfloat16* bh = qhg + (size_t)b * NTOK * C3;
    const __nv_bfloat16* bl = qlg + (size_t)b * NTOK * C3;
    if (tid < HD)
        qs[tid] = __bfloat162float(bh[nh * HD + tid]) + __bfloat162float(bl[nh * HD + tid]);
    __syncthreads();

    for (int n = tid; n < NTOK; n += 256) {
        const __nv_bfloat16* kh = bh + (size_t)n * C3 + C_ + nh * HD;
        const __nv_bfloat16* kl = bl + (size_t)n * C3 + C_ + nh * HD;
        float s = 0.f;
#pragma unroll
        for (int d = 0; d < HD; ++d)
            s += qs[d] * (__bfloat162float(kh[d]) + __bfloat162float(kl[d]));
        scs[n] = s * 0.125f;
    }
    __syncthreads();

    float m = -1e30f;
    for (int n = tid; n < NTOK; n += 256) m = fmaxf(m, scs[n]);
    red[tid] = m;
    __syncthreads();
    for (int st = 128; st; st >>= 1) {
        if (tid < st) red[tid] = fmaxf(red[tid], red[tid + st]);
        __syncthreads();
    }
    m = red[0];
    __syncthreads();

    float s = 0.f;
    for (int n = tid; n < NTOK; n += 256) {
        float e = __expf(scs[n] - m);
        scs[n] = e;
        s += e;
    }
    red[tid] = s;
    __syncthreads();
    for (int st = 128; st; st >>= 1) {
        if (tid < st) red[tid] += red[tid + st];
        __syncthreads();
    }
    const float inv = 1.f / red[0];
    __syncthreads();

    const int d = tid & 63, chunk = tid >> 6;
    float acc = 0.f;
    for (int n = chunk; n < NTOK; n += 4) {
        const size_t voff = (size_t)n * C3 + 2 * C_ + nh * HD + d;
        acc += scs[n] * (__bfloat162float(bh[voff]) + __bfloat162float(bl[voff]));
    }
    part[chunk][d] = acc;
    __syncthreads();
    if (chunk == 0) {
        float r = (part[0][d] + part[1][d] + part[2][d] + part[3][d]) * inv;
        __nv_bfloat16 hh, ll;
        split2(r, hh, ll);
        const size_t ooff = (size_t)b * NTOK * C_ + nh * HD + d;
        outh[ooff] = hh;
        outl[ooff] = ll;
    }
}

// ---------------------------------------------------------------------------
extern "C" void kernel_launch(void* const* d_in, const int* in_sizes, int n_in,
                              void* d_out, int out_size)
{
    const float* x     = (const float*)d_in[0];
    const float* Wqkv  = (const float*)d_in[1];
    const float* Wproj = (const float*)d_in[2];
    const float* bproj = (const float*)d_in[3];
    float* out = (float*)d_out;

    float *att, *sc;
    __nv_bfloat16 *qvh, *qvl, *xh, *xl, *ath, *atl, *wqh, *wql, *wph, *wpl;
    cudaGetSymbolAddress((void**)&qvh, g_qh);
    cudaGetSymbolAddress((void**)&qvl, g_ql);
    cudaGetSymbolAddress((void**)&att, g_att);
    cudaGetSymbolAddress((void**)&sc,  g_sc);
    cudaGetSymbolAddress((void**)&xh,  g_xh);
    cudaGetSymbolAddress((void**)&xl,  g_xl);
    cudaGetSymbolAddress((void**)&ath, g_ath);
    cudaGetSymbolAddress((void**)&atl, g_atl);
    cudaGetSymbolAddress((void**)&wqh, g_wqh);
    cudaGetSymbolAddress((void**)&wql, g_wql);
    cudaGetSymbolAddress((void**)&wph, g_wph);
    cudaGetSymbolAddress((void**)&wpl, g_wpl);

    cudaFuncSetAttribute(gemm_mma,
                         cudaFuncAttributeMaxDynamicSharedMemorySize, GEMM_SMEM);
    cudaFuncSetAttribute(k_rowfused,
                         cudaFuncAttributeMaxDynamicSharedMemorySize, RF_SMEM);

    // 0) pre-passes
    {
        int n4 = MTOT * C_ / 4;
        k_split<<<(n4 + 255) / 256, 256>>>(x, xh, xl, n4);
        k_tsplit<<<dim3(C3 / 32, C_ / 32), dim3(32, 8)>>>(Wqkv,  wqh, wql, C_, C3);
        k_tsplit<<<dim3(C_ / 32, C_ / 32), dim3(32, 8)>>>(Wproj, wph, wpl, C_, C_);
    }
    // 1) QKV projection -> bf16 hi/lo
    gemm_mma<<<dim3(C3 / 128, (MTOT + 127) / 128), 256, GEMM_SMEM>>>(
        xh, xl, wqh, wql, nullptr, nullptr, qvh, qvl, MTOT, C3);
    // 2) attention phases (all MMA)
    {
        dim3 ag(W_, NH_, B_);
        k_colscore<<<ag, 128>>>(qvh, qvl, sc);
        dim3 rg(H_, NH_, B_);
        k_rowfused<<<rg, 128, RF_SMEM>>>(qvh, qvl, sc, att);
        attn_cls<<<B_ * NH_, 256>>>(qvh, qvl, ath, atl);
        k_colagg<<<ag, 128>>>(qvh, qvl, sc, att, ath, atl);
    }
    // 3) output projection + bias (fp32 out)
    gemm_mma<<<dim3(C_ / 128, (MTOT + 127) / 128), 256, GEMM_SMEM>>>(
        ath, atl, wph, wpl, out, bproj, nullptr, nullptr, MTOT, C_);
}

// round 12
// speedup vs baseline: 1.0728x; 1.0728x over previous
#include <cuda_runtime.h>
#include <cuda_bf16.h>
#include <cstdint>

#define H_    56
#define W_    56
#define NH_   12
#define HD    64
#define NTOK  3137          // 56*56 + 1
#define C_    768
#define C3    2304
#define B_    8
#define MTOT  (B_ * NTOK)   // 25096
#define KDIM  768
#define BK    32
#define NSTG  (KDIM / BK)   // 24
#define NCH   8
#define KC    393           // ceil(NTOK / NCH)

typedef unsigned long long u64;

// ---------------- scratch (__device__ globals; no cudaMalloc allowed) -------
__device__ float         g_qkv[(size_t)MTOT * C3];   // fp32 QKV activations
__device__ float         g_att[(size_t)MTOT * C_];   // fp32 row-partial
__device__ float         g_sc [(size_t)B_ * NH_ * H_ * W_ * 64]; // col scores/probs
__device__ float         g_clsp[(size_t)B_ * NH_ * NCH * 66];    // cls partials
__device__ __nv_bfloat16 g_xh [(size_t)MTOT * C_];   // x split hi/lo
__device__ __nv_bfloat16 g_xl [(size_t)MTOT * C_];
__device__ __nv_bfloat16 g_ath[(size_t)MTOT * C_];   // attention out hi/lo
__device__ __nv_bfloat16 g_atl[(size_t)MTOT * C_];
__device__ __nv_bfloat16 g_wqh[(size_t)C3 * C_];     // W_qkv^T split  [N,K]
__device__ __nv_bfloat16 g_wql[(size_t)C3 * C_];
__device__ __nv_bfloat16 g_wph[(size_t)C_ * C_];     // W_proj^T split [N,K]
__device__ __nv_bfloat16 g_wpl[(size_t)C_ * C_];

__device__ __forceinline__ void split2(float v, __nv_bfloat16& h, __nv_bfloat16& l) {
    h = __float2bfloat16(v);
    l = __float2bfloat16(v - __bfloat162float(h));
}
__device__ __forceinline__ uint32_t pack2(__nv_bfloat16 a, __nv_bfloat16 b) {
    return (uint32_t)__bfloat16_as_ushort(a) |
           ((uint32_t)__bfloat16_as_ushort(b) << 16);
}
__device__ __forceinline__ uint32_t su32(const void* p) {
    uint32_t a;
    asm("{ .reg .u64 t; cvta.to.shared.u64 t, %1; cvt.u32.u64 %0, t; }"
        : "=r"(a) : "l"(p));
    return a;
}
__device__ __forceinline__ void cp16(uint32_t dst, const void* src, bool ok) {
    int sz = ok ? 16 : 0;
    asm volatile("cp.async.cg.shared.global [%0], [%1], 16, %2;"
                 :: "r"(dst), "l"(src), "r"(sz) : "memory");
}
__device__ __forceinline__ void mma16816(float* c, const uint32_t* a, const uint32_t* b) {
    asm volatile(
        "mma.sync.aligned.m16n8k16.row.col.f32.bf16.bf16.f32 "
        "{%0,%1,%2,%3}, {%4,%5,%6,%7}, {%8,%9}, {%0,%1,%2,%3};"
        : "+f"(c[0]), "+f"(c[1]), "+f"(c[2]), "+f"(c[3])
        : "r"(a[0]), "r"(a[1]), "r"(a[2]), "r"(a[3]), "r"(b[0]), "r"(b[1]));
}
__device__ __forceinline__ void ldsm4(uint32_t& r0, uint32_t& r1, uint32_t& r2,
                                      uint32_t& r3, uint32_t addr) {
    asm volatile("ldmatrix.sync.aligned.m8n8.x4.shared.b16 {%0,%1,%2,%3}, [%4];"
                 : "=r"(r0), "=r"(r1), "=r"(r2), "=r"(r3) : "r"(addr));
}

// ---------------- packed f32x2 helpers (Blackwell FFMA2) --------------------
__device__ __forceinline__ void fma2(u64& c, u64 a, u64 b) {
    asm("fma.rn.f32x2 %0, %1, %2, %0;" : "+l"(c) : "l"(a), "l"(b));
}
__device__ __forceinline__ float unpack_add(u64 v) {
    float lo, hi;
    asm("mov.b64 {%0,%1}, %2;" : "=f"(lo), "=f"(hi) : "l"(v));
    return lo + hi;
}
__device__ __forceinline__ float2 unpack2(u64 v) {
    float2 r;
    asm("mov.b64 {%0,%1}, %2;" : "=f"(r.x), "=f"(r.y) : "l"(v));
    return r;
}
__device__ __forceinline__ u64 bcast2(float v) {
    u64 r;
    asm("mov.b64 %0, {%1,%1};" : "=l"(r) : "f"(v));
    return r;
}

// ---------------- pre-pass: fp32 -> bf16 hi/lo ------------------------------
__global__ __launch_bounds__(256) void k_split(
    const float* __restrict__ in, __nv_bfloat16* __restrict__ hi,
    __nv_bfloat16* __restrict__ lo, int n4)
{
    int i = blockIdx.x * 256 + threadIdx.x;
    if (i >= n4) return;
    float4 v = ((const float4*)in)[i];
    __nv_bfloat16 hv[4], lv[4];
    split2(v.x, hv[0], lv[0]);
    split2(v.y, hv[1], lv[1]);
    split2(v.z, hv[2], lv[2]);
    split2(v.w, hv[3], lv[3]);
    ((uint2*)hi)[i] = *(uint2*)hv;
    ((uint2*)lo)[i] = *(uint2*)lv;
}

// ---------------- pre-pass: transpose + split weights [R,Cn] -> [Cn,R] ------
__global__ __launch_bounds__(256) void k_tsplit(
    const float* __restrict__ W, __nv_bfloat16* __restrict__ th,
    __nv_bfloat16* __restrict__ tl, int R, int Cn)
{
    __shared__ float t[32][33];
    int x = blockIdx.x * 32 + threadIdx.x;
    int y = blockIdx.y * 32 + threadIdx.y;
#pragma unroll
    for (int j = 0; j < 32; j += 8)
        t[threadIdx.y + j][threadIdx.x] = W[(size_t)(y + j) * Cn + x];
    __syncthreads();
    int ox = blockIdx.y * 32 + threadIdx.x;
    int oy = blockIdx.x * 32 + threadIdx.y;
#pragma unroll
    for (int j = 0; j < 32; j += 8) {
        float v = t[threadIdx.x][threadIdx.y + j];
        __nv_bfloat16 h, l;
        split2(v, h, l);
        th[(size_t)(oy + j) * R + ox] = h;
        tl[(size_t)(oy + j) * R + ox] = l;
    }
}

// ---------------- bf16x3 GEMM: mma.sync + ldmatrix, 3-stage swizzled --------
#define TS2     8192
#define STG2    (4 * TS2)
#define GEMM_SMEM (3 * STG2)

__global__ __launch_bounds__(256) void gemm_mma(
    const __nv_bfloat16* __restrict__ Ah, const __nv_bfloat16* __restrict__ Al,
    const __nv_bfloat16* __restrict__ Bh, const __nv_bfloat16* __restrict__ Bl,
    float* __restrict__ Cc, const float* __restrict__ bias, int M, int N)
{
    extern __shared__ __align__(128) char smem[];
    const uint32_t sb = su32(smem);
    const int tid  = threadIdx.x;
    const int wid  = tid >> 5, lane = tid & 31;
    const int gid  = lane >> 2, tig = lane & 3;
    const int wm   = wid & 1, wn = wid >> 1;
    const int row0 = blockIdx.y * 128, col0 = blockIdx.x * 128;

    float acc[4][4][4];
#pragma unroll
    for (int i = 0; i < 4; ++i)
#pragma unroll
        for (int j = 0; j < 4; ++j)
#pragma unroll
            for (int k = 0; k < 4; ++k) acc[i][j][k] = 0.f;

    const int rlA = (lane & 7) + ((lane >> 3) & 1) * 8;
    const int kcA = (lane >> 4) & 1;
    const int swA = (rlA >> 1) & 3;
    const int rlB = (lane & 7) + ((lane >> 4) & 1) * 8;
    const int kcB = (lane >> 3) & 1;
    const int swB = (rlB >> 1) & 3;
    const uint32_t aRow = (uint32_t)(wm * 64 + rlA) * 64u;
    const uint32_t bRow = (uint32_t)(wn * 32 + rlB) * 64u;

    const int r0c = tid >> 2, j0c = tid & 3;
    const int r1c = (tid + 256) >> 2, j1c = tid & 3;

    auto issue = [&](int c) {
        const int k0 = c * BK;
        const uint32_t stg = sb + (uint32_t)(c % 3) * STG2;
#pragma unroll
        for (int rep = 0; rep < 2; ++rep) {
            const int row = rep ? r1c : r0c;
            const int j   = rep ? j1c : j0c;
            const uint32_t d = stg + (uint32_t)row * 64u
                             + (uint32_t)((j ^ ((row >> 1) & 3)) * 16);
            const int grA = row0 + row;
            const bool okA = grA < M;
            const size_t aoff = (size_t)(okA ? grA : 0) * KDIM + k0 + j * 8;
            cp16(d,           Ah + aoff, okA);
            cp16(d + TS2,     Al + aoff, okA);
            const size_t boff = (size_t)(col0 + row) * KDIM + k0 + j * 8;
            cp16(d + 2 * TS2, Bh + boff, true);
            cp16(d + 3 * TS2, Bl + boff, true);
        }
        asm volatile("cp.async.commit_group;" ::: "memory");
    };

    issue(0);
    issue(1);

    for (int c = 0; c < NSTG; ++c) {
        asm volatile("cp.async.wait_group 1;" ::: "memory");
        __syncthreads();
        if (c + 2 < NSTG) issue(c + 2);

        const uint32_t stg = sb + (uint32_t)(c % 3) * STG2;

#pragma unroll
        for (int kk = 0; kk < 2; ++kk) {
            const uint32_t aCh = (uint32_t)(((kcA + 2 * kk) ^ swA) * 16);
            const uint32_t bCh = (uint32_t)(((kcB + 2 * kk) ^ swB) * 16);
            uint32_t ah[4][4], al[4][4], bh[4][2], bl[4][2];
#pragma unroll
            for (int mt = 0; mt < 4; ++mt) {
                const uint32_t aAd = stg + aRow + mt * (16 * 64) + aCh;
                ldsm4(ah[mt][0], ah[mt][1], ah[mt][2], ah[mt][3], aAd);
                ldsm4(al[mt][0], al[mt][1], al[mt][2], al[mt][3], aAd + TS2);
            }
#pragma unroll
            for (int pr = 0; pr < 2; ++pr) {
                const uint32_t bAd = stg + bRow + pr * (16 * 64) + bCh;
                ldsm4(bh[2 * pr][0], bh[2 * pr][1], bh[2 * pr + 1][0], bh[2 * pr + 1][1],
                      bAd + 2 * TS2);
                ldsm4(bl[2 * pr][0], bl[2 * pr][1], bl[2 * pr + 1][0], bl[2 * pr + 1][1],
                      bAd + 3 * TS2);
            }
#pragma unroll
            for (int mt = 0; mt < 4; ++mt)
#pragma unroll
                for (int nt = 0; nt < 4; ++nt) mma16816(acc[mt][nt], ah[mt], bh[nt]);
#pragma unroll
            for (int mt = 0; mt < 4; ++mt)
#pragma unroll
                for (int nt = 0; nt < 4; ++nt) mma16816(acc[mt][nt], ah[mt], bl[nt]);
#pragma unroll
            for (int mt = 0; mt < 4; ++mt)
#pragma unroll
                for (int nt = 0; nt < 4; ++nt) mma16816(acc[mt][nt], al[mt], bh[nt]);
        }
    }

#pragma unroll
    for (int mt = 0; mt < 4; ++mt) {
        const int gr = row0 + wm * 64 + mt * 16 + gid;
#pragma unroll
        for (int nt = 0; nt < 4; ++nt) {
            const int gc = col0 + wn * 32 + nt * 8 + tig * 2;
            float b0 = 0.f, b1 = 0.f;
            if (bias) { b0 = __ldg(bias + gc); b1 = __ldg(bias + gc + 1); }
            if (gr < M) {
                float2 v0 = make_float2(acc[mt][nt][0] + b0, acc[mt][nt][1] + b1);
                *(float2*)(Cc + (size_t)gr * N + gc) = v0;
            }
            if (gr + 8 < M) {
                float2 v1 = make_float2(acc[mt][nt][2] + b0, acc[mt][nt][3] + b1);
                *(float2*)(Cc + (size_t)(gr + 8) * N + gc) = v1;
            }
        }
    }
}

// ============================================================================
// Attention phase 1: column scores (packed f32x2). Block=(w, head, b).
// ============================================================================
#define QROWS 64
#define SST   68

__global__ __launch_bounds__(128) void k_colscore(
    const float* __restrict__ qkv, float* __restrict__ sc)
{
    __shared__ __align__(16) float Qs[QROWS * SST];
    __shared__ __align__(16) float Ks[QROWS * SST];
    const int w = blockIdx.x, head = blockIdx.y, b = blockIdx.z;
    const int tid = threadIdx.x;
    const float* base = qkv + (size_t)b * NTOK * C3;
    const int qoff = head * HD;

    for (int idx = tid; idx < QROWS * 16; idx += 128) {
        const int r = idx >> 4, c = idx & 15;
        float4 v = make_float4(0.f, 0.f, 0.f, 0.f);
        if (r < 56) {
            const int n = 1 + r * W_ + w;
            v = *(const float4*)(base + (size_t)n * C3 + qoff + c * 4);
        }
        *(float4*)&Qs[r * SST + c * 4] = v;
    }
    for (int idx = tid; idx < QROWS * 16; idx += 128) {
        const int r = idx >> 4, c = idx & 15;
        float4 v = make_float4(0.f, 0.f, 0.f, 0.f);
        if (r < 57) {
            const int n = (r == 0) ? 0 : (1 + (r - 1) * W_ + w);
            v = *(const float4*)(base + (size_t)n * C3 + C_ + qoff + c * 4);
        }
        *(float4*)&Ks[r * SST + c * 4] = v;
    }
    __syncthreads();

    const int ty = tid >> 3, tx = tid & 7;
    u64 acc2[4][8];
#pragma unroll
    for (int i = 0; i < 4; ++i)
#pragma unroll
        for (int j = 0; j < 8; ++j) acc2[i][j] = 0ULL;

#pragma unroll 4
    for (int d = 0; d < HD; d += 4) {
        ulonglong2 a2[4], b2[8];
#pragma unroll
        for (int i = 0; i < 4; ++i)
            a2[i] = *(const ulonglong2*)&Qs[(ty + 16 * i) * SST + d];
#pragma unroll
        for (int j = 0; j < 8; ++j)
            b2[j] = *(const ulonglong2*)&Ks[(tx + 8 * j) * SST + d];
#pragma unroll
        for (int i = 0; i < 4; ++i)
#pragma unroll
            for (int j = 0; j < 8; ++j) {
                fma2(acc2[i][j], a2[i].x, b2[j].x);
                fma2(acc2[i][j], a2[i].y, b2[j].y);
            }
    }

    float* out = sc + ((((size_t)b * NH_ + head) * H_) * W_ + w) * 64;
#pragma unroll
    for (int i = 0; i < 4; ++i) {
        const int hq = ty + 16 * i;
        if (hq >= 56) continue;
#pragma unroll
        for (int j = 0; j < 8; ++j) {
            const int jk = tx + 8 * j;
            if (jk < 57)
                out[(size_t)hq * (W_ * 64) + jk] = unpack_add(acc2[i][j]) * 0.125f;
        }
    }
}

// ============================================================================
// Attention phase 2: row scores + softmax + row aggregation (packed f32x2).
// ============================================================================
#define PST 132
#define K2_SMEM ((2 * QROWS * SST + QROWS * PST) * 4)

__global__ __launch_bounds__(128) void k_rowfused(
    const float* __restrict__ qkv, float* __restrict__ sc,
    float* __restrict__ attp)
{
    extern __shared__ __align__(16) float sm[];
    float* Qs = sm;                       // later reused as Vr
    float* Kr = sm + QROWS * SST;
    float* P  = sm + 2 * QROWS * SST;
    const int h = blockIdx.x, head = blockIdx.y, b = blockIdx.z;
    const int tid = threadIdx.x;
    const float* base = qkv + (size_t)b * NTOK * C3;
    const int qoff = head * HD;
    const int nrow0 = 1 + h * W_;

    for (int idx = tid; idx < QROWS * 16; idx += 128) {
        const int r = idx >> 4, c = idx & 15;
        float4 qv = make_float4(0.f, 0.f, 0.f, 0.f);
        float4 kv = qv;
        if (r < 56) {
            const float* tok = base + (size_t)(nrow0 + r) * C3;
            qv = *(const float4*)(tok + qoff + c * 4);
            kv = *(const float4*)(tok + C_ + qoff + c * 4);
        }
        *(float4*)&Qs[r * SST + c * 4] = qv;
        *(float4*)&Kr[r * SST + c * 4] = kv;
    }
    __syncthreads();

    const int ty = tid >> 3, tx = tid & 7;
    // row scores (packed along reduction dim)
    {
        u64 acc2[4][8];
#pragma unroll
        for (int i = 0; i < 4; ++i)
#pragma unroll
            for (int j = 0; j < 8; ++j) acc2[i][j] = 0ULL;
#pragma unroll 4
        for (int d = 0; d < HD; d += 4) {
            ulonglong2 a2[4], b2[8];
#pragma unroll
            for (int i = 0; i < 4; ++i)
                a2[i] = *(const ulonglong2*)&Qs[(ty + 16 * i) * SST + d];
#pragma unroll
            for (int j = 0; j < 8; ++j)
                b2[j] = *(const ulonglong2*)&Kr[(tx + 8 * j) * SST + d];
#pragma unroll
            for (int i = 0; i < 4; ++i)
#pragma unroll
                for (int j = 0; j < 8; ++j) {
                    fma2(acc2[i][j], a2[i].x, b2[j].x);
                    fma2(acc2[i][j], a2[i].y, b2[j].y);
                }
        }
#pragma unroll
        for (int i = 0; i < 4; ++i) {
            const int q = ty + 16 * i;
#pragma unroll
            for (int j = 0; j < 8; ++j) {
                const int k = tx + 8 * j;
                float v = unpack_add(acc2[i][j]) * 0.125f;
                P[q * PST + 60 + k] = (k == q) ? -1e30f : v;
            }
        }
    }
    __syncthreads();

    // reload Vr into Qs space; pull col scores into P[:, 0..56]
    for (int idx = tid; idx < 56 * 16; idx += 128) {
        const int r = idx >> 4, c = idx & 15;
        *(float4*)&Qs[r * SST + c * 4] =
            *(const float4*)(base + (size_t)(nrow0 + r) * C3 + 2 * C_ + qoff + c * 4);
    }
    {
        const float* scb = sc + ((((size_t)b * NH_ + head) * H_ + h) * W_) * 64;
        for (int idx = tid; idx < 56 * 57; idx += 128) {
            const int q = idx / 57, j = idx % 57;
            P[q * PST + j] = scb[(size_t)q * 64 + j];
        }
    }
    __syncthreads();

    // softmax over 113 entries per query
    if (tid < 56) {
        float* row = P + tid * PST;
        float m = -1e30f;
#pragma unroll 4
        for (int j = 0; j < 57; ++j) m = fmaxf(m, row[j]);
#pragma unroll 4
        for (int j = 60; j < 116; ++j) m = fmaxf(m, row[j]);
        float s = 0.f;
#pragma unroll 4
        for (int j = 0; j < 57; ++j) { float e = __expf(row[j] - m); row[j] = e; s += e; }
#pragma unroll 4
        for (int j = 60; j < 116; ++j) { float e = __expf(row[j] - m); row[j] = e; s += e; }
        const float inv = 1.f / s;
#pragma unroll 4
        for (int j = 0; j < 57; ++j) row[j] *= inv;
#pragma unroll 4
        for (int j = 60; j < 116; ++j) row[j] *= inv;
    }
    __syncthreads();

    // write normalized col probs back
    {
        float* scb = sc + ((((size_t)b * NH_ + head) * H_ + h) * W_) * 64;
        for (int idx = tid; idx < 56 * 57; idx += 128) {
            const int q = idx / 57, j = idx % 57;
            scb[(size_t)q * 64 + j] = P[q * PST + j];
        }
    }

    // row aggregation: out[q][d] = sum_k P[q][60+k] * Vr[k][d]
    // packed along output dim d: thread owns col pairs 2*tx + 16*j2
    {
        u64 acc2[4][4];
#pragma unroll
        for (int i = 0; i < 4; ++i)
#pragma unroll
            for (int j = 0; j < 4; ++j) acc2[i][j] = 0ULL;
        for (int k = 0; k < 56; ++k) {
            u64 pa[4], vb[4];
#pragma unroll
            for (int i = 0; i < 4; ++i) pa[i] = bcast2(P[(ty + 16 * i) * PST + 60 + k]);
#pragma unroll
            for (int j2 = 0; j2 < 4; ++j2)
                vb[j2] = *(const u64*)&Qs[k * SST + 2 * tx + 16 * j2];
#pragma unroll
            for (int i = 0; i < 4; ++i)
#pragma unroll
                for (int j2 = 0; j2 < 4; ++j2) fma2(acc2[i][j2], pa[i], vb[j2]);
        }
#pragma unroll
        for (int i = 0; i < 4; ++i) {
            const int q = ty + 16 * i;
            if (q >= 56) continue;
            float* op = attp + ((size_t)b * NTOK + nrow0 + q) * C_ + qoff;
#pragma unroll
            for (int j2 = 0; j2 < 4; ++j2)
                *(float2*)(op + 2 * tx + 16 * j2) = unpack2(acc2[i][j2]);
        }
    }
}

// ============================================================================
// Attention phase 3: column aggregation (packed f32x2) + final hi/lo emit.
// ============================================================================
__global__ __launch_bounds__(128) void k_colagg(
    const float* __restrict__ qkv, const float* __restrict__ sc,
    const float* __restrict__ attp,
    __nv_bfloat16* __restrict__ outh, __nv_bfloat16* __restrict__ outl)
{
    __shared__ __align__(16) float Vc[57 * SST];
    __shared__ __align__(16) float Pc[64 * 60];
    const int w = blockIdx.x, head = blockIdx.y, b = blockIdx.z;
    const int tid = threadIdx.x;
    const float* base = qkv + (size_t)b * NTOK * C3;
    const int qoff = head * HD;

    for (int idx = tid; idx < 57 * 16; idx += 128) {
        const int r = idx >> 4, c = idx & 15;
        const int n = (r == 0) ? 0 : (1 + (r - 1) * W_ + w);
        *(float4*)&Vc[r * SST + c * 4] =
            *(const float4*)(base + (size_t)n * C3 + 2 * C_ + qoff + c * 4);
    }
    {
        const float* scb = sc + (((size_t)b * NH_ + head) * H_) * (W_ * 64) + (size_t)w * 64;
        for (int idx = tid; idx < 56 * 57; idx += 128) {
            const int q = idx / 57, j = idx % 57;
            Pc[q * 60 + j] = scb[(size_t)q * (W_ * 64) + j];
        }
    }
    __syncthreads();

    const int ty = tid >> 3, tx = tid & 7;
    u64 acc2[4][4];
#pragma unroll
    for (int i = 0; i < 4; ++i)
#pragma unroll
        for (int j = 0; j < 4; ++j) acc2[i][j] = 0ULL;
    for (int k = 0; k < 57; ++k) {
        u64 pa[4], vb[4];
#pragma unroll
        for (int i = 0; i < 4; ++i) pa[i] = bcast2(Pc[(ty + 16 * i) * 60 + k]);
#pragma unroll
        for (int j2 = 0; j2 < 4; ++j2)
            vb[j2] = *(const u64*)&Vc[k * SST + 2 * tx + 16 * j2];
#pragma unroll
        for (int i = 0; i < 4; ++i)
#pragma unroll
            for (int j2 = 0; j2 < 4; ++j2) fma2(acc2[i][j2], pa[i], vb[j2]);
    }
#pragma unroll
    for (int i = 0; i < 4; ++i) {
        const int hq = ty + 16 * i;
        if (hq >= 56) continue;
        const size_t off = ((size_t)b * NTOK + 1 + hq * W_ + w) * C_ + qoff;
#pragma unroll
        for (int j2 = 0; j2 < 4; ++j2) {
            const int col = 2 * tx + 16 * j2;
            float2 v = unpack2(acc2[i][j2]);
            const float2 rp = *(const float2*)(attp + off + col);
            __nv_bfloat16 h0, l0, h1, l1;
            split2(v.x + rp.x, h0, l0);
            split2(v.y + rp.y, h1, l1);
            *(uint32_t*)(outh + off + col) = pack2(h0, h1);
            *(uint32_t*)(outl + off + col) = pack2(l0, l1);
        }
    }
}

// ---------------- CLS-token attention: split-K partials + reduce ------------
__global__ __launch_bounds__(256) void cls_part(
    const float* __restrict__ qkv, float* __restrict__ clsp)
{
    const int nh = blockIdx.x, b = blockIdx.y, ch = blockIdx.z;
    const int tid = threadIdx.x;
    const int n0 = ch * KC;
    const int n1 = min(NTOK, n0 + KC);
    const int cnt = n1 - n0;

    __shared__ float qs[HD];
    __shared__ float scs[KC];
    __shared__ float red[256];
    __shared__ float part[4][HD];

    const float* base = qkv + (size_t)b * NTOK * C3;
    if (tid < HD) qs[tid] = base[nh * HD + tid];
    __syncthreads();

    for (int i = tid; i < cnt; i += 256) {
        const float* kp = base + (size_t)(n0 + i) * C3 + C_ + nh * HD;
        float s = 0.f;
#pragma unroll
        for (int d = 0; d < HD; ++d) s += qs[d] * kp[d];
        scs[i] = s * 0.125f;
    }
    __syncthreads();

    float m = -1e30f;
    for (int i = tid; i < cnt; i += 256) m = fmaxf(m, scs[i]);
    red[tid] = m;
    __syncthreads();
    for (int st = 128; st; st >>= 1) {
        if (tid < st) red[tid] = fmaxf(red[tid], red[tid + st]);
        __syncthreads();
    }
    m = red[0];
    __syncthreads();

    float s = 0.f;
    for (int i = tid; i < cnt; i += 256) {
        float e = __expf(scs[i] - m);
        scs[i] = e;
        s += e;
    }
    red[tid] = s;
    __syncthreads();
    for (int st = 128; st; st >>= 1) {
        if (tid < st) red[tid] += red[tid + st];
        __syncthreads();
    }
    const float S = red[0];
    __syncthreads();

    const int d = tid & 63, kq = tid >> 6;
    float acc = 0.f;
    for (int i = kq; i < cnt; i += 4)
        acc += scs[i] * base[(size_t)(n0 + i) * C3 + 2 * C_ + nh * HD + d];
    part[kq][d] = acc;
    __syncthreads();
    if (kq == 0) {
        float* o = clsp + ((size_t)(b * NH_ + nh) * NCH + ch) * 66;
        o[d] = part[0][d] + part[1][d] + part[2][d] + part[3][d];
        if (d == 0) { o[64] = m; o[65] = S; }
    }
}

__global__ __launch_bounds__(64) void cls_reduce(
    const float* __restrict__ clsp,
    __nv_bfloat16* __restrict__ outh, __nv_bfloat16* __restrict__ outl)
{
    const int nh = blockIdx.x, b = blockIdx.y;
    const int d = threadIdx.x;
    const float* o = clsp + (size_t)(b * NH_ + nh) * NCH * 66;
    float M = -1e30f;
#pragma unroll
    for (int c = 0; c < NCH; ++c) M = fmaxf(M, o[c * 66 + 64]);
    float S = 0.f, A = 0.f;
#pragma unroll
    for (int c = 0; c < NCH; ++c) {
        const float wgt = __expf(o[c * 66 + 64] - M);
        S += o[c * 66 + 65] * wgt;
        A += o[c * 66 + d] * wgt;
    }
    const float r = A / S;
    __nv_bfloat16 hh, ll;
    split2(r, hh, ll);
    const size_t ooff = (size_t)b * NTOK * C_ + nh * HD + d;
    outh[ooff] = hh;
    outl[ooff] = ll;
}

// ---------------------------------------------------------------------------
extern "C" void kernel_launch(void* const* d_in, const int* in_sizes, int n_in,
                              void* d_out, int out_size)
{
    const float* x     = (const float*)d_in[0];
    const float* Wqkv  = (const float*)d_in[1];
    const float* Wproj = (const float*)d_in[2];
    const float* bproj = (const float*)d_in[3];
    float* out = (float*)d_out;

    float *qkv, *att, *sc, *clsp;
    __nv_bfloat16 *xh, *xl, *ath, *atl, *wqh, *wql, *wph, *wpl;
    cudaGetSymbolAddress((void**)&qkv,  g_qkv);
    cudaGetSymbolAddress((void**)&att,  g_att);
    cudaGetSymbolAddress((void**)&sc,   g_sc);
    cudaGetSymbolAddress((void**)&clsp, g_clsp);
    cudaGetSymbolAddress((void**)&xh,   g_xh);
    cudaGetSymbolAddress((void**)&xl,   g_xl);
    cudaGetSymbolAddress((void**)&ath,  g_ath);
    cudaGetSymbolAddress((void**)&atl,  g_atl);
    cudaGetSymbolAddress((void**)&wqh,  g_wqh);
    cudaGetSymbolAddress((void**)&wql,  g_wql);
    cudaGetSymbolAddress((void**)&wph,  g_wph);
    cudaGetSymbolAddress((void**)&wpl,  g_wpl);

    cudaFuncSetAttribute(gemm_mma,
                         cudaFuncAttributeMaxDynamicSharedMemorySize, GEMM_SMEM);
    cudaFuncSetAttribute(k_rowfused,
                         cudaFuncAttributeMaxDynamicSharedMemorySize, K2_SMEM);

    // 0) pre-passes
    {
        int n4 = MTOT * C_ / 4;
        k_split<<<(n4 + 255) / 256, 256>>>(x, xh, xl, n4);
        k_tsplit<<<dim3(C3 / 32, C_ / 32), dim3(32, 8)>>>(Wqkv,  wqh, wql, C_, C3);
        k_tsplit<<<dim3(C_ / 32, C_ / 32), dim3(32, 8)>>>(Wproj, wph, wpl, C_, C_);
    }
    // 1) QKV projection (HMMA bf16x3, 3-stage swizzled pipeline)
    gemm_mma<<<dim3(C3 / 128, (MTOT + 127) / 128), 256, GEMM_SMEM>>>(
        xh, xl, wqh, wql, qkv, nullptr, MTOT, C3);
    // 2) attention phases
    {
        dim3 ag(W_, NH_, B_);
        k_colscore<<<ag, 128>>>(qkv, sc);
        dim3 rg(H_, NH_, B_);
        k_rowfused<<<rg, 128, K2_SMEM>>>(qkv, sc, att);
        cls_part<<<dim3(NH_, B_, NCH), 256>>>(qkv, clsp);
        cls_reduce<<<dim3(NH_, B_), 64>>>(clsp, ath, atl);
        k_colagg<<<ag, 128>>>(qkv, sc, att, ath, atl);
    }
    // 3) output projection + bias (HMMA bf16x3, 3-stage swizzled pipeline)
    gemm_mma<<<dim3(C_ / 128, (MTOT + 127) / 128), 256, GEMM_SMEM>>>(
        ath, atl, wph, wpl, out, bproj, MTOT, C_);
}

// round 13
// speedup vs baseline: 1.2691x; 1.1830x over previous
#include <cuda_runtime.h>
#include <cuda_bf16.h>
#include <cuda_fp16.h>
#include <cstdint>

#define H_    56
#define W_    56
#define NH_   12
#define HD    64
#define NTOK  3137          // 56*56 + 1
#define C_    768
#define C3    2304
#define B_    8
#define MTOT  (B_ * NTOK)   // 25096
#define KDIM  768
#define BK    32
#define NSTG  (KDIM / BK)   // 24
#define NCH   8
#define KC    393           // ceil(NTOK / NCH)

typedef unsigned long long u64;

// ---------------- scratch (__device__ globals; no cudaMalloc allowed) -------
__device__ float  g_qkv[(size_t)MTOT * C3];   // fp32 QKV activations
__device__ float  g_att[(size_t)MTOT * C_];   // fp32 row-partial
__device__ float  g_sc [(size_t)B_ * NH_ * H_ * W_ * 64]; // col scores/probs
__device__ float  g_clsp[(size_t)B_ * NH_ * NCH * 66];    // cls partials
__device__ __half g_xh [(size_t)MTOT * C_];   // x in fp16
__device__ __half g_ath[(size_t)MTOT * C_];   // attention out fp16
__device__ __half g_wqh[(size_t)C3 * C_];     // W_qkv^T split  [N,K]
__device__ __half g_wql[(size_t)C3 * C_];
__device__ __half g_wph[(size_t)C_ * C_];     // W_proj^T split [N,K]
__device__ __half g_wpl[(size_t)C_ * C_];

__device__ __forceinline__ void hsplit2(float v, __half& h, __half& l) {
    h = __float2half(v);
    l = __float2half(v - __half2float(h));
}
__device__ __forceinline__ uint32_t hpack2(__half a, __half b) {
    return (uint32_t)__half_as_ushort(a) |
           ((uint32_t)__half_as_ushort(b) << 16);
}
__device__ __forceinline__ uint32_t su32(const void* p) {
    uint32_t a;
    asm("{ .reg .u64 t; cvta.to.shared.u64 t, %1; cvt.u32.u64 %0, t; }"
        : "=r"(a) : "l"(p));
    return a;
}
__device__ __forceinline__ void cp16(uint32_t dst, const void* src, bool ok) {
    int sz = ok ? 16 : 0;
    asm volatile("cp.async.cg.shared.global [%0], [%1], 16, %2;"
                 :: "r"(dst), "l"(src), "r"(sz) : "memory");
}
__device__ __forceinline__ void mma16816(float* c, const uint32_t* a, const uint32_t* b) {
    asm volatile(
        "mma.sync.aligned.m16n8k16.row.col.f32.f16.f16.f32 "
        "{%0,%1,%2,%3}, {%4,%5,%6,%7}, {%8,%9}, {%0,%1,%2,%3};"
        : "+f"(c[0]), "+f"(c[1]), "+f"(c[2]), "+f"(c[3])
        : "r"(a[0]), "r"(a[1]), "r"(a[2]), "r"(a[3]), "r"(b[0]), "r"(b[1]));
}
__device__ __forceinline__ void ldsm4(uint32_t& r0, uint32_t& r1, uint32_t& r2,
                                      uint32_t& r3, uint32_t addr) {
    asm volatile("ldmatrix.sync.aligned.m8n8.x4.shared.b16 {%0,%1,%2,%3}, [%4];"
                 : "=r"(r0), "=r"(r1), "=r"(r2), "=r"(r3) : "r"(addr));
}

// ---------------- packed f32x2 helpers (Blackwell FFMA2) --------------------
__device__ __forceinline__ void fma2(u64& c, u64 a, u64 b) {
    asm("fma.rn.f32x2 %0, %1, %2, %0;" : "+l"(c) : "l"(a), "l"(b));
}
__device__ __forceinline__ float unpack_add(u64 v) {
    float lo, hi;
    asm("mov.b64 {%0,%1}, %2;" : "=f"(lo), "=f"(hi) : "l"(v));
    return lo + hi;
}
__device__ __forceinline__ float2 unpack2(u64 v) {
    float2 r;
    asm("mov.b64 {%0,%1}, %2;" : "=f"(r.x), "=f"(r.y) : "l"(v));
    return r;
}
__device__ __forceinline__ u64 bcast2(float v) {
    u64 r;
    asm("mov.b64 %0, {%1,%1};" : "=l"(r) : "f"(v));
    return r;
}

// ---------------- pre-pass: fp32 -> fp16 ------------------------------------
__global__ __launch_bounds__(256) void k_split(
    const float* __restrict__ in, __half* __restrict__ hi, int n4)
{
    int i = blockIdx.x * 256 + threadIdx.x;
    if (i >= n4) return;
    float4 v = ((const float4*)in)[i];
    __half hv[4];
    hv[0] = __float2half(v.x);
    hv[1] = __float2half(v.y);
    hv[2] = __float2half(v.z);
    hv[3] = __float2half(v.w);
    ((uint2*)hi)[i] = *(uint2*)hv;
}

// ---------------- pre-pass: transpose + fp16 split weights ------------------
__global__ __launch_bounds__(256) void k_tsplit(
    const float* __restrict__ W, __half* __restrict__ th,
    __half* __restrict__ tl, int R, int Cn)
{
    __shared__ float t[32][33];
    int x = blockIdx.x * 32 + threadIdx.x;
    int y = blockIdx.y * 32 + threadIdx.y;
#pragma unroll
    for (int j = 0; j < 32; j += 8)
        t[threadIdx.y + j][threadIdx.x] = W[(size_t)(y + j) * Cn + x];
    __syncthreads();
    int ox = blockIdx.y * 32 + threadIdx.x;
    int oy = blockIdx.x * 32 + threadIdx.y;
#pragma unroll
    for (int j = 0; j < 32; j += 8) {
        float v = t[threadIdx.x][threadIdx.y + j];
        __half h, l;
        hsplit2(v, h, l);
        th[(size_t)(oy + j) * R + ox] = h;
        tl[(size_t)(oy + j) * R + ox] = l;
    }
}

// ---------------- fp16x2 GEMM: C = Ah[M,K] @ (Bh+Bl)[N,K]^T (+bias) ---------
// 3-stage pipeline, 3 tensors per stage (Ah, Bh, Bl), XOR-swizzled 64B rows.
#define TS2     8192                 // one 128x32 fp16 tile
#define STG2    (3 * TS2)            // 24 KB per stage
#define GEMM_SMEM (3 * STG2)         // 72 KB

__global__ __launch_bounds__(256) void gemm_mma(
    const __half* __restrict__ Ah,
    const __half* __restrict__ Bh, const __half* __restrict__ Bl,
    float* __restrict__ Cc, const float* __restrict__ bias, int M, int N)
{
    extern __shared__ __align__(128) char smem[];
    const uint32_t sb = su32(smem);
    const int tid  = threadIdx.x;
    const int wid  = tid >> 5, lane = tid & 31;
    const int gid  = lane >> 2, tig = lane & 3;
    const int wm   = wid & 1, wn = wid >> 1;          // 2 x 4 warp grid
    const int row0 = blockIdx.y * 128, col0 = blockIdx.x * 128;

    float acc[4][4][4];
#pragma unroll
    for (int i = 0; i < 4; ++i)
#pragma unroll
        for (int j = 0; j < 4; ++j)
#pragma unroll
            for (int k = 0; k < 4; ++k) acc[i][j][k] = 0.f;

    const int rlA = (lane & 7) + ((lane >> 3) & 1) * 8;
    const int kcA = (lane >> 4) & 1;
    const int swA = (rlA >> 1) & 3;
    const int rlB = (lane & 7) + ((lane >> 4) & 1) * 8;
    const int kcB = (lane >> 3) & 1;
    const int swB = (rlB >> 1) & 3;
    const uint32_t aRow = (uint32_t)(wm * 64 + rlA) * 64u;
    const uint32_t bRow = (uint32_t)(wn * 32 + rlB) * 64u;

    const int r0c = tid >> 2, j0c = tid & 3;
    const int r1c = (tid + 256) >> 2, j1c = tid & 3;

    auto issue = [&](int c) {
        const int k0 = c * BK;
        const uint32_t stg = sb + (uint32_t)(c % 3) * STG2;
#pragma unroll
        for (int rep = 0; rep < 2; ++rep) {
            const int row = rep ? r1c : r0c;
            const int j   = rep ? j1c : j0c;
            const uint32_t d = stg + (uint32_t)row * 64u
                             + (uint32_t)((j ^ ((row >> 1) & 3)) * 16);
            const int grA = row0 + row;
            const bool okA = grA < M;
            const size_t aoff = (size_t)(okA ? grA : 0) * KDIM + k0 + j * 8;
            cp16(d, Ah + aoff, okA);
            const size_t boff = (size_t)(col0 + row) * KDIM + k0 + j * 8;
            cp16(d + TS2,     Bh + boff, true);
            cp16(d + 2 * TS2, Bl + boff, true);
        }
        asm volatile("cp.async.commit_group;" ::: "memory");
    };

    issue(0);
    issue(1);

    for (int c = 0; c < NSTG; ++c) {
        asm volatile("cp.async.wait_group 1;" ::: "memory");
        __syncthreads();
        if (c + 2 < NSTG) issue(c + 2);

        const uint32_t stg = sb + (uint32_t)(c % 3) * STG2;

#pragma unroll
        for (int kk = 0; kk < 2; ++kk) {
            const uint32_t aCh = (uint32_t)(((kcA + 2 * kk) ^ swA) * 16);
            const uint32_t bCh = (uint32_t)(((kcB + 2 * kk) ^ swB) * 16);
            uint32_t ah[4][4], bh[4][2], bl[4][2];
#pragma unroll
            for (int mt = 0; mt < 4; ++mt) {
                const uint32_t aAd = stg + aRow + mt * (16 * 64) + aCh;
                ldsm4(ah[mt][0], ah[mt][1], ah[mt][2], ah[mt][3], aAd);
            }
#pragma unroll
            for (int pr = 0; pr < 2; ++pr) {
                const uint32_t bAd = stg + bRow + pr * (16 * 64) + bCh;
                ldsm4(bh[2 * pr][0], bh[2 * pr][1], bh[2 * pr + 1][0], bh[2 * pr + 1][1],
                      bAd + TS2);
                ldsm4(bl[2 * pr][0], bl[2 * pr][1], bl[2 * pr + 1][0], bl[2 * pr + 1][1],
                      bAd + 2 * TS2);
            }
#pragma unroll
            for (int mt = 0; mt < 4; ++mt)
#pragma unroll
                for (int nt = 0; nt < 4; ++nt) mma16816(acc[mt][nt], ah[mt], bh[nt]);
#pragma unroll
            for (int mt = 0; mt < 4; ++mt)
#pragma unroll
                for (int nt = 0; nt < 4; ++nt) mma16816(acc[mt][nt], ah[mt], bl[nt]);
        }
    }

#pragma unroll
    for (int mt = 0; mt < 4; ++mt) {
        const int gr = row0 + wm * 64 + mt * 16 + gid;
#pragma unroll
        for (int nt = 0; nt < 4; ++nt) {
            const int gc = col0 + wn * 32 + nt * 8 + tig * 2;
            float b0 = 0.f, b1 = 0.f;
            if (bias) { b0 = __ldg(bias + gc); b1 = __ldg(bias + gc + 1); }
            if (gr < M) {
                float2 v0 = make_float2(acc[mt][nt][0] + b0, acc[mt][nt][1] + b1);
                *(float2*)(Cc + (size_t)gr * N + gc) = v0;
            }
            if (gr + 8 < M) {
                float2 v1 = make_float2(acc[mt][nt][2] + b0, acc[mt][nt][3] + b1);
                *(float2*)(Cc + (size_t)(gr + 8) * N + gc) = v1;
            }
        }
    }
}

// ============================================================================
// Attention phase 1: column scores (packed f32x2). Block=(w, head, b).
// ============================================================================
#define QROWS 64
#define SST   68

__global__ __launch_bounds__(128) void k_colscore(
    const float* __restrict__ qkv, float* __restrict__ sc)
{
    __shared__ __align__(16) float Qs[QROWS * SST];
    __shared__ __align__(16) float Ks[QROWS * SST];
    const int w = blockIdx.x, head = blockIdx.y, b = blockIdx.z;
    const int tid = threadIdx.x;
    const float* base = qkv + (size_t)b * NTOK * C3;
    const int qoff = head * HD;

    for (int idx = tid; idx < QROWS * 16; idx += 128) {
        const int r = idx >> 4, c = idx & 15;
        float4 v = make_float4(0.f, 0.f, 0.f, 0.f);
        if (r < 56) {
            const int n = 1 + r * W_ + w;
            v = *(const float4*)(base + (size_t)n * C3 + qoff + c * 4);
        }
        *(float4*)&Qs[r * SST + c * 4] = v;
    }
    for (int idx = tid; idx < QROWS * 16; idx += 128) {
        const int r = idx >> 4, c = idx & 15;
        float4 v = make_float4(0.f, 0.f, 0.f, 0.f);
        if (r < 57) {
            const int n = (r == 0) ? 0 : (1 + (r - 1) * W_ + w);
            v = *(const float4*)(base + (size_t)n * C3 + C_ + qoff + c * 4);
        }
        *(float4*)&Ks[r * SST + c * 4] = v;
    }
    __syncthreads();

    const int ty = tid >> 3, tx = tid & 7;
    u64 acc2[4][8];
#pragma unroll
    for (int i = 0; i < 4; ++i)
#pragma unroll
        for (int j = 0; j < 8; ++j) acc2[i][j] = 0ULL;

#pragma unroll 4
    for (int d = 0; d < HD; d += 4) {
        ulonglong2 a2[4], b2[8];
#pragma unroll
        for (int i = 0; i < 4; ++i)
            a2[i] = *(const ulonglong2*)&Qs[(ty + 16 * i) * SST + d];
#pragma unroll
        for (int j = 0; j < 8; ++j)
            b2[j] = *(const ulonglong2*)&Ks[(tx + 8 * j) * SST + d];
#pragma unroll
        for (int i = 0; i < 4; ++i)
#pragma unroll
            for (int j = 0; j < 8; ++j) {
                fma2(acc2[i][j], a2[i].x, b2[j].x);
                fma2(acc2[i][j], a2[i].y, b2[j].y);
            }
    }

    float* out = sc + ((((size_t)b * NH_ + head) * H_) * W_ + w) * 64;
#pragma unroll
    for (int i = 0; i < 4; ++i) {
        const int hq = ty + 16 * i;
        if (hq >= 56) continue;
#pragma unroll
        for (int j = 0; j < 8; ++j) {
            const int jk = tx + 8 * j;
            if (jk < 57)
                out[(size_t)hq * (W_ * 64) + jk] = unpack_add(acc2[i][j]) * 0.125f;
        }
    }
}

// ============================================================================
// Attention phase 2: row scores + softmax + row aggregation (packed f32x2).
// ============================================================================
#define PST 132
#define K2_SMEM ((2 * QROWS * SST + QROWS * PST) * 4)

__global__ __launch_bounds__(128) void k_rowfused(
    const float* __restrict__ qkv, float* __restrict__ sc,
    float* __restrict__ attp)
{
    extern __shared__ __align__(16) float sm[];
    float* Qs = sm;                       // later reused as Vr
    float* Kr = sm + QROWS * SST;
    float* P  = sm + 2 * QROWS * SST;
    const int h = blockIdx.x, head = blockIdx.y, b = blockIdx.z;
    const int tid = threadIdx.x;
    const float* base = qkv + (size_t)b * NTOK * C3;
    const int qoff = head * HD;
    const int nrow0 = 1 + h * W_;

    for (int idx = tid; idx < QROWS * 16; idx += 128) {
        const int r = idx >> 4, c = idx & 15;
        float4 qv = make_float4(0.f, 0.f, 0.f, 0.f);
        float4 kv = qv;
        if (r < 56) {
            const float* tok = base + (size_t)(nrow0 + r) * C3;
            qv = *(const float4*)(tok + qoff + c * 4);
            kv = *(const float4*)(tok + C_ + qoff + c * 4);
        }
        *(float4*)&Qs[r * SST + c * 4] = qv;
        *(float4*)&Kr[r * SST + c * 4] = kv;
    }
    __syncthreads();

    const int ty = tid >> 3, tx = tid & 7;
    {
        u64 acc2[4][8];
#pragma unroll
        for (int i = 0; i < 4; ++i)
#pragma unroll
            for (int j = 0; j < 8; ++j) acc2[i][j] = 0ULL;
#pragma unroll 4
        for (int d = 0; d < HD; d += 4) {
            ulonglong2 a2[4], b2[8];
#pragma unroll
            for (int i = 0; i < 4; ++i)
                a2[i] = *(const ulonglong2*)&Qs[(ty + 16 * i) * SST + d];
#pragma unroll
            for (int j = 0; j < 8; ++j)
                b2[j] = *(const ulonglong2*)&Kr[(tx + 8 * j) * SST + d];
#pragma unroll
            for (int i = 0; i < 4; ++i)
#pragma unroll
                for (int j = 0; j < 8; ++j) {
                    fma2(acc2[i][j], a2[i].x, b2[j].x);
                    fma2(acc2[i][j], a2[i].y, b2[j].y);
                }
        }
#pragma unroll
        for (int i = 0; i < 4; ++i) {
            const int q = ty + 16 * i;
#pragma unroll
            for (int j = 0; j < 8; ++j) {
                const int k = tx + 8 * j;
                float v = unpack_add(acc2[i][j]) * 0.125f;
                P[q * PST + 60 + k] = (k == q) ? -1e30f : v;
            }
        }
    }
    __syncthreads();

    for (int idx = tid; idx < 56 * 16; idx += 128) {
        const int r = idx >> 4, c = idx & 15;
        *(float4*)&Qs[r * SST + c * 4] =
            *(const float4*)(base + (size_t)(nrow0 + r) * C3 + 2 * C_ + qoff + c * 4);
    }
    {
        const float* scb = sc + ((((size_t)b * NH_ + head) * H_ + h) * W_) * 64;
        for (int idx = tid; idx < 56 * 57; idx += 128) {
            const int q = idx / 57, j = idx % 57;
            P[q * PST + j] = scb[(size_t)q * 64 + j];
        }
    }
    __syncthreads();

    if (tid < 56) {
        float* row = P + tid * PST;
        float m = -1e30f;
#pragma unroll 4
        for (int j = 0; j < 57; ++j) m = fmaxf(m, row[j]);
#pragma unroll 4
        for (int j = 60; j < 116; ++j) m = fmaxf(m, row[j]);
        float s = 0.f;
#pragma unroll 4
        for (int j = 0; j < 57; ++j) { float e = __expf(row[j] - m); row[j] = e; s += e; }
#pragma unroll 4
        for (int j = 60; j < 116; ++j) { float e = __expf(row[j] - m); row[j] = e; s += e; }
        const float inv = 1.f / s;
#pragma unroll 4
        for (int j = 0; j < 57; ++j) row[j] *= inv;
#pragma unroll 4
        for (int j = 60; j < 116; ++j) row[j] *= inv;
    }
    __syncthreads();

    {
        float* scb = sc + ((((size_t)b * NH_ + head) * H_ + h) * W_) * 64;
        for (int idx = tid; idx < 56 * 57; idx += 128) {
            const int q = idx / 57, j = idx % 57;
            scb[(size_t)q * 64 + j] = P[q * PST + j];
        }
    }

    {
        u64 acc2[4][4];
#pragma unroll
        for (int i = 0; i < 4; ++i)
#pragma unroll
            for (int j = 0; j < 4; ++j) acc2[i][j] = 0ULL;
        for (int k = 0; k < 56; ++k) {
            u64 pa[4], vb[4];
#pragma unroll
            for (int i = 0; i < 4; ++i) pa[i] = bcast2(P[(ty + 16 * i) * PST + 60 + k]);
#pragma unroll
            for (int j2 = 0; j2 < 4; ++j2)
                vb[j2] = *(const u64*)&Qs[k * SST + 2 * tx + 16 * j2];
#pragma unroll
            for (int i = 0; i < 4; ++i)
#pragma unroll
                for (int j2 = 0; j2 < 4; ++j2) fma2(acc2[i][j2], pa[i], vb[j2]);
        }
#pragma unroll
        for (int i = 0; i < 4; ++i) {
            const int q = ty + 16 * i;
            if (q >= 56) continue;
            float* op = attp + ((size_t)b * NTOK + nrow0 + q) * C_ + qoff;
#pragma unroll
            for (int j2 = 0; j2 < 4; ++j2)
                *(float2*)(op + 2 * tx + 16 * j2) = unpack2(acc2[i][j2]);
        }
    }
}

// ============================================================================
// Attention phase 3: column aggregation (packed f32x2) + fp16 emit.
// ============================================================================
__global__ __launch_bounds__(128) void k_colagg(
    const float* __restrict__ qkv, const float* __restrict__ sc,
    const float* __restrict__ attp, __half* __restrict__ outh)
{
    __shared__ __align__(16) float Vc[57 * SST];
    __shared__ __align__(16) float Pc[64 * 60];
    const int w = blockIdx.x, head = blockIdx.y, b = blockIdx.z;
    const int tid = threadIdx.x;
    const float* base = qkv + (size_t)b * NTOK * C3;
    const int qoff = head * HD;

    for (int idx = tid; idx < 57 * 16; idx += 128) {
        const int r = idx >> 4, c = idx & 15;
        const int n = (r == 0) ? 0 : (1 + (r - 1) * W_ + w);
        *(float4*)&Vc[r * SST + c * 4] =
            *(const float4*)(base + (size_t)n * C3 + 2 * C_ + qoff + c * 4);
    }
    {
        const float* scb = sc + (((size_t)b * NH_ + head) * H_) * (W_ * 64) + (size_t)w * 64;
        for (int idx = tid; idx < 56 * 57; idx += 128) {
            const int q = idx / 57, j = idx % 57;
            Pc[q * 60 + j] = scb[(size_t)q * (W_ * 64) + j];
        }
    }
    __syncthreads();

    const int ty = tid >> 3, tx = tid & 7;
    u64 acc2[4][4];
#pragma unroll
    for (int i = 0; i < 4; ++i)
#pragma unroll
        for (int j = 0; j < 4; ++j) acc2[i][j] = 0ULL;
    for (int k = 0; k < 57; ++k) {
        u64 pa[4], vb[4];
#pragma unroll
        for (int i = 0; i < 4; ++i) pa[i] = bcast2(Pc[(ty + 16 * i) * 60 + k]);
#pragma unroll
        for (int j2 = 0; j2 < 4; ++j2)
            vb[j2] = *(const u64*)&Vc[k * SST + 2 * tx + 16 * j2];
#pragma unroll
        for (int i = 0; i < 4; ++i)
#pragma unroll
            for (int j2 = 0; j2 < 4; ++j2) fma2(acc2[i][j2], pa[i], vb[j2]);
    }
#pragma unroll
    for (int i = 0; i < 4; ++i) {
        const int hq = ty + 16 * i;
        if (hq >= 56) continue;
        const size_t off = ((size_t)b * NTOK + 1 + hq * W_ + w) * C_ + qoff;
#pragma unroll
        for (int j2 = 0; j2 < 4; ++j2) {
            const int col = 2 * tx + 16 * j2;
            float2 v = unpack2(acc2[i][j2]);
            const float2 rp = *(const float2*)(attp + off + col);
            *(uint32_t*)(outh + off + col) =
                hpack2(__float2half(v.x + rp.x), __float2half(v.y + rp.y));
        }
    }
}

// ---------------- CLS-token attention: split-K partials + reduce ------------
__global__ __launch_bounds__(256) void cls_part(
    const float* __restrict__ qkv, float* __restrict__ clsp)
{
    const int nh = blockIdx.x, b = blockIdx.y, ch = blockIdx.z;
    const int tid = threadIdx.x;
    const int n0 = ch * KC;
    const int n1 = min(NTOK, n0 + KC);
    const int cnt = n1 - n0;

    __shared__ float qs[HD];
    __shared__ float scs[KC];
    __shared__ float red[256];
    __shared__ float part[4][HD];

    const float* base = qkv + (size_t)b * NTOK * C3;
    if (tid < HD) qs[tid] = base[nh * HD + tid];
    __syncthreads();

    for (int i = tid; i < cnt; i += 256) {
        const float* kp = base + (size_t)(n0 + i) * C3 + C_ + nh * HD;
        float s = 0.f;
#pragma unroll
        for (int d = 0; d < HD; ++d) s += qs[d] * kp[d];
        scs[i] = s * 0.125f;
    }
    __syncthreads();

    float m = -1e30f;
    for (int i = tid; i < cnt; i += 256) m = fmaxf(m, scs[i]);
    red[tid] = m;
    __syncthreads();
    for (int st = 128; st; st >>= 1) {
        if (tid < st) red[tid] = fmaxf(red[tid], red[tid + st]);
        __syncthreads();
    }
    m = red[0];
    __syncthreads();

    float s = 0.f;
    for (int i = tid; i < cnt; i += 256) {
        float e = __expf(scs[i] - m);
        scs[i] = e;
        s += e;
    }
    red[tid] = s;
    __syncthreads();
    for (int st = 128; st; st >>= 1) {
        if (tid < st) red[tid] += red[tid + st];
        __syncthreads();
    }
    const float S = red[0];
    __syncthreads();

    const int d = tid & 63, kq = tid >> 6;
    float acc = 0.f;
    for (int i = kq; i < cnt; i += 4)
        acc += scs[i] * base[(size_t)(n0 + i) * C3 + 2 * C_ + nh * HD + d];
    part[kq][d] = acc;
    __syncthreads();
    if (kq == 0) {
        float* o = clsp + ((size_t)(b * NH_ + nh) * NCH + ch) * 66;
        o[d] = part[0][d] + part[1][d] + part[2][d] + part[3][d];
        if (d == 0) { o[64] = m; o[65] = S; }
    }
}

__global__ __launch_bounds__(64) void cls_reduce(
    const float* __restrict__ clsp, __half* __restrict__ outh)
{
    const int nh = blockIdx.x, b = blockIdx.y;
    const int d = threadIdx.x;
    const float* o = clsp + (size_t)(b * NH_ + nh) * NCH * 66;
    float M = -1e30f;
#pragma unroll
    for (int c = 0; c < NCH; ++c) M = fmaxf(M, o[c * 66 + 64]);
    float S = 0.f, A = 0.f;
#pragma unroll
    for (int c = 0; c < NCH; ++c) {
        const float wgt = __expf(o[c * 66 + 64] - M);
        S += o[c * 66 + 65] * wgt;
        A += o[c * 66 + d] * wgt;
    }
    outh[(size_t)b * NTOK * C_ + nh * HD + d] = __float2half(A / S);
}

// ---------------------------------------------------------------------------
extern "C" void kernel_launch(void* const* d_in, const int* in_sizes, int n_in,
                              void* d_out, int out_size)
{
    const float* x     = (const float*)d_in[0];
    const float* Wqkv  = (const float*)d_in[1];
    const float* Wproj = (const float*)d_in[2];
    const float* bproj = (const float*)d_in[3];
    float* out = (float*)d_out;

    float *qkv, *att, *sc, *clsp;
    __half *xh, *ath, *wqh, *wql, *wph, *wpl;
    cudaGetSymbolAddress((void**)&qkv,  g_qkv);
    cudaGetSymbolAddress((void**)&att,  g_att);
    cudaGetSymbolAddress((void**)&sc,   g_sc);
    cudaGetSymbolAddress((void**)&clsp, g_clsp);
    cudaGetSymbolAddress((void**)&xh,   g_xh);
    cudaGetSymbolAddress((void**)&ath,  g_ath);
    cudaGetSymbolAddress((void**)&wqh,  g_wqh);
    cudaGetSymbolAddress((void**)&wql,  g_wql);
    cudaGetSymbolAddress((void**)&wph,  g_wph);
    cudaGetSymbolAddress((void**)&wpl,  g_wpl);

    cudaFuncSetAttribute(gemm_mma,
                         cudaFuncAttributeMaxDynamicSharedMemorySize, GEMM_SMEM);
    cudaFuncSetAttribute(k_rowfused,
                         cudaFuncAttributeMaxDynamicSharedMemorySize, K2_SMEM);

    // 0) pre-passes
    {
        int n4 = MTOT * C_ / 4;
        k_split<<<(n4 + 255) / 256, 256>>>(x, xh, n4);
        k_tsplit<<<dim3(C3 / 32, C_ / 32), dim3(32, 8)>>>(Wqkv,  wqh, wql, C_, C3);
        k_tsplit<<<dim3(C_ / 32, C_ / 32), dim3(32, 8)>>>(Wproj, wph, wpl, C_, C_);
    }
    // 1) QKV projection (HMMA fp16x2, 3-stage swizzled pipeline)
    gemm_mma<<<dim3(C3 / 128, (MTOT + 127) / 128), 256, GEMM_SMEM>>>(
        xh, wqh, wql, qkv, nullptr, MTOT, C3);
    // 2) attention phases
    {
        dim3 ag(W_, NH_, B_);
        k_colscore<<<ag, 128>>>(qkv, sc);
        dim3 rg(H_, NH_, B_);
        k_rowfused<<<rg, 128, K2_SMEM>>>(qkv, sc, att);
        cls_part<<<dim3(NH_, B_, NCH), 256>>>(qkv, clsp);
        cls_reduce<<<dim3(NH_, B_), 64>>>(clsp, ath);
        k_colagg<<<ag, 128>>>(qkv, sc, att, ath);
    }
    // 3) output projection + bias (HMMA fp16x2)
    gemm_mma<<<dim3(C_ / 128, (MTOT + 127) / 128), 256, GEMM_SMEM>>>(
        ath, wph, wpl, out, bproj, MTOT, C_);
}